// round 1
// baseline (speedup 1.0000x reference)
#include <cuda_runtime.h>
#include <cstdint>

#define NSPOT 50000
#define NGENE 2000
#define HID   64
#define NEDGE 800000
#define BN_EPS 1e-5f

// ---------------- device scratch (no allocation allowed) ----------------
__device__ float g_z[NSPOT * HID];        // encoder pre-BN
__device__ float g_uself[NSPOT * HID];    // relu(h@Ws1+bs1)
__device__ float g_agg[NSPOT * HID];      // neighbor sum -> then relu(h_agg@We1+be1) in place
__device__ int   g_cnt[NSPOT];
__device__ float g_part[500 * 128];       // BN partials: 500 blocks x (64 sum + 64 sumsq)
__device__ float g_mean[HID];
__device__ float g_rstd[HID];

// ---------------- generic tiled SGEMM with bias: C = A@B + bias --------
// A: [M,K] row-major, B: [K,N] row-major, bias: [N]
template<int BM, int BN, int BK, int TM, int TN>
__global__ __launch_bounds__(256)
void sgemm_bias(const float* __restrict__ A, const float* __restrict__ B,
                const float* __restrict__ bias, float* __restrict__ C,
                int M, int N, int K)
{
    __shared__ __align__(16) float As[BK][BM + 4];   // stored transposed [k][m]
    __shared__ __align__(16) float Bs[BK][BN + 4];

    const int tid = threadIdx.x;
    const int ntx = BN / TN;               // threads along N
    const int tx = tid % ntx;
    const int ty = tid / ntx;
    const int rowBase = blockIdx.y * BM;
    const int colBase = blockIdx.x * BN;

    float acc[TM][TN];
#pragma unroll
    for (int i = 0; i < TM; i++)
#pragma unroll
        for (int j = 0; j < TN; j++) acc[i][j] = 0.f;

    for (int k0 = 0; k0 < K; k0 += BK) {
        // load A tile (BM x BK) into As[k][m]
        for (int i = tid; i < BM * BK; i += 256) {
            int m = i / BK, kk = i % BK;
            int gr = rowBase + m, gc = k0 + kk;
            As[kk][m] = (gr < M && gc < K) ? A[(size_t)gr * K + gc] : 0.f;
        }
        // load B tile (BK x BN) into Bs[k][n]
        for (int i = tid; i < BK * BN; i += 256) {
            int kk = i / BN, n = i % BN;
            int gr = k0 + kk, gc = colBase + n;
            Bs[kk][n] = (gr < K && gc < N) ? B[(size_t)gr * N + gc] : 0.f;
        }
        __syncthreads();
#pragma unroll
        for (int kk = 0; kk < BK; kk++) {
            float a[TM], b[TN];
#pragma unroll
            for (int i = 0; i < TM; i += 4) {
                float4 t = *reinterpret_cast<const float4*>(&As[kk][ty * TM + i]);
                a[i] = t.x; a[i+1] = t.y; a[i+2] = t.z; a[i+3] = t.w;
            }
#pragma unroll
            for (int j = 0; j < TN; j += 4) {
                float4 t = *reinterpret_cast<const float4*>(&Bs[kk][tx * TN + j]);
                b[j] = t.x; b[j+1] = t.y; b[j+2] = t.z; b[j+3] = t.w;
            }
#pragma unroll
            for (int i = 0; i < TM; i++)
#pragma unroll
                for (int j = 0; j < TN; j++)
                    acc[i][j] = fmaf(a[i], b[j], acc[i][j]);
        }
        __syncthreads();
    }
#pragma unroll
    for (int i = 0; i < TM; i++) {
        int r = rowBase + ty * TM + i;
        if (r >= M) continue;
#pragma unroll
        for (int j = 0; j < TN; j++) {
            int c = colBase + tx * TN + j;
            if (c < N) C[(size_t)r * N + c] = acc[i][j] + bias[c];
        }
    }
}

// ---------------- BatchNorm statistics (deterministic 2-stage) ----------
__global__ void bn_stage1(const float* __restrict__ z)
{
    const int c = threadIdx.x;                // 64 threads
    const int b = blockIdx.x;                 // 500 blocks
    const int r0 = b * 100;
    float s = 0.f, ss = 0.f;
    for (int r = r0; r < r0 + 100; r++) {
        float v = z[(size_t)r * HID + c];
        s += v; ss += v * v;
    }
    g_part[b * 128 + c] = s;
    g_part[b * 128 + 64 + c] = ss;
}

__global__ void bn_stage2()
{
    const int c = threadIdx.x;                // 64 threads, 1 block
    float s = 0.f, ss = 0.f;
    for (int b = 0; b < 500; b++) {
        s += g_part[b * 128 + c];
        ss += g_part[b * 128 + 64 + c];
    }
    float mu = s / (float)NSPOT;
    float var = ss / (float)NSPOT - mu * mu;
    g_mean[c] = mu;
    g_rstd[c] = rsqrtf(var + BN_EPS);
}

// ---------------- encoder tail: BN+ReLU then h = zr@W2 + b2 -------------
__global__ __launch_bounds__(256)
void enc_tail(const float* __restrict__ gamma, const float* __restrict__ beta,
              const float* __restrict__ W2, const float* __restrict__ b2,
              float* __restrict__ h_out)
{
    __shared__ float sW[HID * HID];
    __shared__ float sbuf[8][HID];
    const int tid = threadIdx.x;
    for (int i = tid; i < HID * HID; i += 256) sW[i] = W2[i];
    const int lane = tid & 31, warp = tid >> 5;
    const int c0 = lane, c1 = lane + 32;
    const float m0 = g_mean[c0], m1 = g_mean[c1];
    const float r0 = g_rstd[c0], r1 = g_rstd[c1];
    const float ga0 = gamma[c0], ga1 = gamma[c1];
    const float bt0 = beta[c0],  bt1 = beta[c1];
    const float bb0 = b2[c0],    bb1 = b2[c1];
    __syncthreads();
    const int nw = gridDim.x * 8;
    for (int row = blockIdx.x * 8 + warp; row < NSPOT; row += nw) {
        const float* zr = g_z + (size_t)row * HID;
        float v0 = fmaxf(fmaf((zr[c0] - m0) * r0, ga0, bt0), 0.f);
        float v1 = fmaxf(fmaf((zr[c1] - m1) * r1, ga1, bt1), 0.f);
        sbuf[warp][c0] = v0; sbuf[warp][c1] = v1;
        __syncwarp();
        float a0 = bb0, a1 = bb1;
#pragma unroll
        for (int k = 0; k < HID; k++) {
            float s = sbuf[warp][k];
            a0 = fmaf(s, sW[k * HID + c0], a0);
            a1 = fmaf(s, sW[k * HID + c1], a1);
        }
        h_out[(size_t)row * HID + c0] = a0;
        h_out[(size_t)row * HID + c1] = a1;
        __syncwarp();
    }
}

// ---------------- heads: pos_pred and u_self from h ---------------------
__global__ __launch_bounds__(256)
void heads_small(const float* __restrict__ h_in,
                 const float* __restrict__ Wp1, const float* __restrict__ bp1,
                 const float* __restrict__ Wp2, const float* __restrict__ bp2,
                 const float* __restrict__ Ws1, const float* __restrict__ bs1,
                 float* __restrict__ pos_out)
{
    __shared__ float sWp1[HID * HID];
    __shared__ float sWs1[HID * HID];
    __shared__ float sWp2[HID * 2];
    __shared__ float sbuf[8][HID];
    __shared__ float pbuf[8][HID];
    const int tid = threadIdx.x;
    for (int i = tid; i < HID * HID; i += 256) { sWp1[i] = Wp1[i]; sWs1[i] = Ws1[i]; }
    if (tid < HID * 2) sWp2[tid] = Wp2[tid];
    const int lane = tid & 31, warp = tid >> 5;
    const int c0 = lane, c1 = lane + 32;
    const float bp0 = bp1[c0], bp1v = bp1[c1];
    const float bs0 = bs1[c0], bs1v = bs1[c1];
    __syncthreads();
    const int nw = gridDim.x * 8;
    for (int row = blockIdx.x * 8 + warp; row < NSPOT; row += nw) {
        const float* hr = h_in + (size_t)row * HID;
        sbuf[warp][c0] = hr[c0]; sbuf[warp][c1] = hr[c1];
        __syncwarp();
        float p0 = bp0, p1 = bp1v, u0 = bs0, u1 = bs1v;
#pragma unroll
        for (int k = 0; k < HID; k++) {
            float s = sbuf[warp][k];
            p0 = fmaf(s, sWp1[k * HID + c0], p0);
            p1 = fmaf(s, sWp1[k * HID + c1], p1);
            u0 = fmaf(s, sWs1[k * HID + c0], u0);
            u1 = fmaf(s, sWs1[k * HID + c1], u1);
        }
        pbuf[warp][c0] = fmaxf(p0, 0.f);
        pbuf[warp][c1] = fmaxf(p1, 0.f);
        g_uself[(size_t)row * HID + c0] = fmaxf(u0, 0.f);
        g_uself[(size_t)row * HID + c1] = fmaxf(u1, 0.f);
        __syncwarp();
        if (lane < 2) {
            float acc = bp2[lane];
#pragma unroll
            for (int k = 0; k < HID; k++)
                acc = fmaf(pbuf[warp][k], sWp2[k * 2 + lane], acc);
            pos_out[(size_t)row * 2 + lane] = acc;
        }
        __syncwarp();
    }
}

// ---------------- edge aggregation ---------------------------------------
__global__ void zero_scratch()
{
    int i = blockIdx.x * blockDim.x + threadIdx.x;
    if (i < NSPOT * HID) g_agg[i] = 0.f;
    if (i < NSPOT) g_cnt[i] = 0;
}

__global__ void scatter_h(const float* __restrict__ h, const int* __restrict__ ei)
{
    long t = (long)blockIdx.x * blockDim.x + threadIdx.x;
    if (t >= (long)NEDGE * 16) return;
    int e = (int)(t >> 4), p = (int)(t & 15);
    int src = ei[e];
    int dst = ei[NEDGE + e];
    float4 v = *reinterpret_cast<const float4*>(h + (size_t)src * HID + p * 4);
    float* a = g_agg + (size_t)dst * HID + p * 4;
    if (p == 0) atomicAdd(&g_cnt[dst], 1);
    asm volatile("red.global.add.v4.f32 [%0], {%1,%2,%3,%4};"
                 :: "l"(a), "f"(v.x), "f"(v.y), "f"(v.z), "f"(v.w) : "memory");
}

// mean-normalize aggregate, then u_nb = relu(h_agg@We1 + be1) in place
__global__ __launch_bounds__(256)
void agg_mlp(const float* __restrict__ We1, const float* __restrict__ be1)
{
    __shared__ float sW[HID * HID];
    __shared__ float sbuf[8][HID];
    const int tid = threadIdx.x;
    for (int i = tid; i < HID * HID; i += 256) sW[i] = We1[i];
    const int lane = tid & 31, warp = tid >> 5;
    const int c0 = lane, c1 = lane + 32;
    const float be0 = be1[c0], be1v = be1[c1];
    __syncthreads();
    const int nw = gridDim.x * 8;
    for (int row = blockIdx.x * 8 + warp; row < NSPOT; row += nw) {
        float inv = 1.0f / fmaxf((float)g_cnt[row], 1.0f);
        float* ar = g_agg + (size_t)row * HID;
        sbuf[warp][c0] = ar[c0] * inv;
        sbuf[warp][c1] = ar[c1] * inv;
        __syncwarp();
        float a0 = be0, a1 = be1v;
#pragma unroll
        for (int k = 0; k < HID; k++) {
            float s = sbuf[warp][k];
            a0 = fmaf(s, sW[k * HID + c0], a0);
            a1 = fmaf(s, sW[k * HID + c1], a1);
        }
        ar[c0] = fmaxf(a0, 0.f);
        ar[c1] = fmaxf(a1, 0.f);
        __syncwarp();
    }
}

// ---------------- launch ---------------------------------------------------
extern "C" void kernel_launch(void* const* d_in, const int* in_sizes, int n_in,
                              void* d_out, int out_size)
{
    const float* x     = (const float*)d_in[0];
    const int*   ei    = (const int*)  d_in[1];
    const float* W1    = (const float*)d_in[2];
    const float* b1    = (const float*)d_in[3];
    const float* gamma = (const float*)d_in[4];
    const float* beta  = (const float*)d_in[5];
    const float* W2    = (const float*)d_in[6];
    const float* b2    = (const float*)d_in[7];
    const float* Wp1   = (const float*)d_in[8];
    const float* bp1   = (const float*)d_in[9];
    const float* Wp2   = (const float*)d_in[10];
    const float* bp2   = (const float*)d_in[11];
    const float* Ws1   = (const float*)d_in[12];
    const float* bs1   = (const float*)d_in[13];
    const float* Ws2   = (const float*)d_in[14];
    const float* bs2   = (const float*)d_in[15];
    const float* We1   = (const float*)d_in[16];
    const float* be1   = (const float*)d_in[17];
    const float* We2   = (const float*)d_in[18];
    const float* be2   = (const float*)d_in[19];

    float* out = (float*)d_out;
    float* h_out   = out;                                 // [50000, 64]
    float* pos_out = out + (size_t)NSPOT * HID;           // [50000, 2]
    float* xs_out  = pos_out + (size_t)NSPOT * 2;         // [50000, 2000]
    float* xn_out  = xs_out + (size_t)NSPOT * NGENE;      // [50000, 2000]

    float* zp;   cudaGetSymbolAddress((void**)&zp, g_z);
    float* usp;  cudaGetSymbolAddress((void**)&usp, g_uself);
    float* aggp; cudaGetSymbolAddress((void**)&aggp, g_agg);

    // 1. z = x @ W1 + b1
    {
        dim3 grid(1, (NSPOT + 127) / 128);
        sgemm_bias<128, 64, 16, 8, 4><<<grid, 256>>>(x, W1, b1, zp, NSPOT, HID, NGENE);
    }
    // 2. BN statistics
    bn_stage1<<<500, 64>>>(zp);
    bn_stage2<<<1, 64>>>();
    // 3. BN+ReLU -> h
    enc_tail<<<1184, 256>>>(gamma, beta, W2, b2, h_out);
    // 4. pos_pred + u_self
    heads_small<<<1184, 256>>>(h_out, Wp1, bp1, Wp2, bp2, Ws1, bs1, pos_out);
    // 5. neighbor aggregation
    zero_scratch<<<(NSPOT * HID + 255) / 256, 256>>>();
    {
        long tot = (long)NEDGE * 16;
        scatter_h<<<(int)((tot + 255) / 256), 256>>>(h_out, ei);
    }
    agg_mlp<<<1184, 256>>>(We1, be1);
    // 6. big output GEMMs: [50000,64] @ [64,2000]
    {
        dim3 grid((NGENE + 127) / 128, (NSPOT + 63) / 64);
        sgemm_bias<64, 128, 32, 4, 8><<<grid, 256>>>(usp, Ws2, bs2, xs_out, NSPOT, NGENE, HID);
        sgemm_bias<64, 128, 32, 4, 8><<<grid, 256>>>(aggp, We2, be2, xn_out, NSPOT, NGENE, HID);
    }
    (void)in_sizes; (void)n_in; (void)out_size;
}

// round 4
// speedup vs baseline: 2.6822x; 2.6822x over previous
#include <cuda_runtime.h>
#include <cstdint>

#define NSPOT 50000
#define NGENE 2000
#define HID   64
#define NEDGE 800000
#define BN_EPS 1e-5f

// ---------------- device scratch (no allocation allowed) ----------------
__device__ float g_z[NSPOT * HID];        // z, then relu(BN(z)), then u_nb
__device__ float g_uself[NSPOT * HID];    // relu(h@Ws1+bs1)
__device__ float g_agg[NSPOT * HID];      // u_pos, then neighbor sum/mean
__device__ int   g_cnt[NSPOT];
__device__ float g_part[500 * 128];
__device__ float g_mean[HID];
__device__ float g_rstd[HID];

// ---------------- tf32 helpers ------------------------------------------
__device__ __forceinline__ uint32_t f2tf(float f) {
    uint32_t r; asm("cvt.rna.tf32.f32 %0, %1;" : "=r"(r) : "f"(f)); return r;
}
__device__ __forceinline__ void mma8(float* c, const uint32_t* a, const uint32_t* b) {
    asm volatile(
        "mma.sync.aligned.m16n8k8.row.col.f32.tf32.tf32.f32 "
        "{%0,%1,%2,%3}, {%4,%5,%6,%7}, {%8,%9}, {%0,%1,%2,%3};"
        : "+f"(c[0]), "+f"(c[1]), "+f"(c[2]), "+f"(c[3])
        : "r"(a[0]), "r"(a[1]), "r"(a[2]), "r"(a[3]), "r"(b[0]), "r"(b[1]));
}

// ---------------- TF32 tensor-core GEMM: C = A@B + bias (opt relu) ------
// A: [M,K] row-major fp32, B: [K,N] row-major fp32, C: [M,N] fp32.
// Requires K % BK == 0, K % 4 == 0, N % 4 == 0. M, N may be ragged vs tiles.
template<int BM, int BN, int BK, bool RELU>
__global__ __launch_bounds__(256)
void gemm_tf32(const float* __restrict__ A, const float* __restrict__ B,
               const float* __restrict__ bias, float* __restrict__ C,
               int M, int N, int K)
{
    constexpr int WARPS_N = BN / 32;          // 2 (BN=64) or 4 (BN=128)
    constexpr int WARPS_M = 8 / WARPS_N;      // 4 or 2
    constexpr int WM = BM / WARPS_M;          // 32 or 64
    constexpr int MT = WM / 16;               // 2 or 4
    constexpr int NT = 4;                     // WN = 32 always
    constexpr int ASTR = BK + 4;              // smem row stride (conflict-free)
    constexpr int BSTR = BN + 8;

    __shared__ __align__(16) uint32_t As[BM * ASTR];
    __shared__ __align__(16) uint32_t Bs[BK * BSTR];

    const int tid = threadIdx.x;
    const int lane = tid & 31, wid = tid >> 5;
    const int g = lane >> 2, tg = lane & 3;
    const int rowBase = blockIdx.y * BM;
    const int colBase = blockIdx.x * BN;
    const int mW = (wid / WARPS_N) * WM;
    const int nW = (wid % WARPS_N) * 32;

    float acc[MT][NT][4];
#pragma unroll
    for (int i = 0; i < MT; i++)
#pragma unroll
        for (int j = 0; j < NT; j++)
#pragma unroll
            for (int q = 0; q < 4; q++) acc[i][j][q] = 0.f;

    for (int k0 = 0; k0 < K; k0 += BK) {
        // --- A tile: BM x BK, float4 along K, cvt to tf32 ---
#pragma unroll 2
        for (int i = tid; i < BM * (BK / 4); i += 256) {
            int m = i / (BK / 4), k4 = (i % (BK / 4)) * 4;
            int r = rowBase + m;
            uint4 v = {0u, 0u, 0u, 0u};
            if (r < M) {
                float4 f = *reinterpret_cast<const float4*>(A + (size_t)r * K + k0 + k4);
                v.x = f2tf(f.x); v.y = f2tf(f.y); v.z = f2tf(f.z); v.w = f2tf(f.w);
            }
            *reinterpret_cast<uint4*>(&As[m * ASTR + k4]) = v;
        }
        // --- B tile: BK x BN ---
#pragma unroll 2
        for (int i = tid; i < BK * (BN / 4); i += 256) {
            int kk = i / (BN / 4), n4 = (i % (BN / 4)) * 4;
            int c = colBase + n4;
            uint4 v = {0u, 0u, 0u, 0u};
            if (c < N) {
                float4 f = *reinterpret_cast<const float4*>(B + (size_t)(k0 + kk) * N + c);
                v.x = f2tf(f.x); v.y = f2tf(f.y); v.z = f2tf(f.z); v.w = f2tf(f.w);
            }
            *reinterpret_cast<uint4*>(&Bs[kk * BSTR + n4]) = v;
        }
        __syncthreads();
#pragma unroll
        for (int ks = 0; ks < BK / 8; ks++) {
            uint32_t a[MT][4], b[NT][2];
#pragma unroll
            for (int i = 0; i < MT; i++) {
                int r0 = mW + i * 16 + g;
                a[i][0] = As[r0 * ASTR + ks * 8 + tg];
                a[i][1] = As[(r0 + 8) * ASTR + ks * 8 + tg];
                a[i][2] = As[r0 * ASTR + ks * 8 + tg + 4];
                a[i][3] = As[(r0 + 8) * ASTR + ks * 8 + tg + 4];
            }
#pragma unroll
            for (int j = 0; j < NT; j++) {
                b[j][0] = Bs[(ks * 8 + tg) * BSTR + nW + j * 8 + g];
                b[j][1] = Bs[(ks * 8 + tg + 4) * BSTR + nW + j * 8 + g];
            }
#pragma unroll
            for (int i = 0; i < MT; i++)
#pragma unroll
                for (int j = 0; j < NT; j++)
                    mma8(acc[i][j], a[i], b[j]);
        }
        __syncthreads();
    }

    // --- epilogue: bias (+relu), float2 stores ---
#pragma unroll
    for (int i = 0; i < MT; i++) {
        int r0 = rowBase + mW + i * 16 + g;
        int r1 = r0 + 8;
#pragma unroll
        for (int j = 0; j < NT; j++) {
            int c = colBase + nW + j * 8 + tg * 2;
            if (c >= N) continue;
            float bi0 = __ldg(bias + c), bi1 = __ldg(bias + c + 1);
            if (r0 < M) {
                float o0 = acc[i][j][0] + bi0, o1 = acc[i][j][1] + bi1;
                if (RELU) { o0 = fmaxf(o0, 0.f); o1 = fmaxf(o1, 0.f); }
                *reinterpret_cast<float2*>(C + (size_t)r0 * N + c) = make_float2(o0, o1);
            }
            if (r1 < M) {
                float o2 = acc[i][j][2] + bi0, o3 = acc[i][j][3] + bi1;
                if (RELU) { o2 = fmaxf(o2, 0.f); o3 = fmaxf(o3, 0.f); }
                *reinterpret_cast<float2*>(C + (size_t)r1 * N + c) = make_float2(o2, o3);
            }
        }
    }
}

// ---------------- BatchNorm statistics (deterministic 2-stage) ----------
__global__ void bn_stage1(const float* __restrict__ z)
{
    const int c = threadIdx.x;
    const int b = blockIdx.x;
    const int r0 = b * 100;
    float s = 0.f, ss = 0.f;
    for (int r = r0; r < r0 + 100; r++) {
        float v = z[(size_t)r * HID + c];
        s += v; ss += v * v;
    }
    g_part[b * 128 + c] = s;
    g_part[b * 128 + 64 + c] = ss;
}

__global__ void bn_stage2()
{
    const int c = threadIdx.x;
    float s = 0.f, ss = 0.f;
    for (int b = 0; b < 500; b++) {
        s += g_part[b * 128 + c];
        ss += g_part[b * 128 + 64 + c];
    }
    float mu = s / (float)NSPOT;
    float var = ss / (float)NSPOT - mu * mu;
    g_mean[c] = mu;
    g_rstd[c] = rsqrtf(var + BN_EPS);
}

// ---------------- elementwise BN + ReLU (in place on g_z) ---------------
__global__ __launch_bounds__(256)
void bn_relu_ew(const float* __restrict__ gamma, const float* __restrict__ beta)
{
    int i = blockIdx.x * blockDim.x + threadIdx.x;   // over NSPOT*16 float4s
    if (i >= NSPOT * (HID / 4)) return;
    int c4 = (i & 15) * 4;
    float4* p = reinterpret_cast<float4*>(g_z) + i;
    float4 v = *p;
    float4 o;
    o.x = fmaxf(fmaf((v.x - g_mean[c4+0]) * g_rstd[c4+0], gamma[c4+0], beta[c4+0]), 0.f);
    o.y = fmaxf(fmaf((v.y - g_mean[c4+1]) * g_rstd[c4+1], gamma[c4+1], beta[c4+1]), 0.f);
    o.z = fmaxf(fmaf((v.z - g_mean[c4+2]) * g_rstd[c4+2], gamma[c4+2], beta[c4+2]), 0.f);
    o.w = fmaxf(fmaf((v.w - g_mean[c4+3]) * g_rstd[c4+3], gamma[c4+3], beta[c4+3]), 0.f);
    *p = o;
}

// ---------------- pos head: pos = u_pos @ Wp2 + bp2 ([64,2]) ------------
__global__ __launch_bounds__(256)
void pos_head(const float* __restrict__ upos, const float* __restrict__ Wp2,
              const float* __restrict__ bp2, float* __restrict__ pos)
{
    int gw = (blockIdx.x * blockDim.x + threadIdx.x) >> 5;
    int lane = threadIdx.x & 31;
    if (gw >= NSPOT) return;
    float v0 = upos[(size_t)gw * HID + lane];
    float v1 = upos[(size_t)gw * HID + lane + 32];
    float p0 = v0 * __ldg(Wp2 + lane * 2)       + v1 * __ldg(Wp2 + (lane + 32) * 2);
    float p1 = v0 * __ldg(Wp2 + lane * 2 + 1)   + v1 * __ldg(Wp2 + (lane + 32) * 2 + 1);
#pragma unroll
    for (int o = 16; o > 0; o >>= 1) {
        p0 += __shfl_xor_sync(0xffffffffu, p0, o);
        p1 += __shfl_xor_sync(0xffffffffu, p1, o);
    }
    if (lane == 0) {
        pos[(size_t)gw * 2]     = p0 + __ldg(bp2);
        pos[(size_t)gw * 2 + 1] = p1 + __ldg(bp2 + 1);
    }
}

// ---------------- edge aggregation ---------------------------------------
__global__ void zero_scratch()
{
    int i = blockIdx.x * blockDim.x + threadIdx.x;
    if (i < NSPOT * HID) g_agg[i] = 0.f;
    if (i < NSPOT) g_cnt[i] = 0;
}

__global__ void scatter_h(const float* __restrict__ h, const int* __restrict__ ei)
{
    long t = (long)blockIdx.x * blockDim.x + threadIdx.x;
    if (t >= (long)NEDGE * 16) return;
    int e = (int)(t >> 4), p = (int)(t & 15);
    int src = ei[e];
    int dst = ei[NEDGE + e];
    float4 v = *reinterpret_cast<const float4*>(h + (size_t)src * HID + p * 4);
    float* a = g_agg + (size_t)dst * HID + p * 4;
    if (p == 0) atomicAdd(&g_cnt[dst], 1);
    asm volatile("red.global.add.v4.f32 [%0], {%1,%2,%3,%4};"
                 :: "l"(a), "f"(v.x), "f"(v.y), "f"(v.z), "f"(v.w) : "memory");
}

__global__ __launch_bounds__(256)
void mean_ew()
{
    int i = blockIdx.x * blockDim.x + threadIdx.x;   // over NSPOT*16 float4s
    if (i >= NSPOT * (HID / 4)) return;
    int row = i >> 4;
    float inv = 1.0f / fmaxf((float)g_cnt[row], 1.0f);
    float4* p = reinterpret_cast<float4*>(g_agg) + i;
    float4 v = *p;
    v.x *= inv; v.y *= inv; v.z *= inv; v.w *= inv;
    *p = v;
}

// ---------------- launch ---------------------------------------------------
extern "C" void kernel_launch(void* const* d_in, const int* in_sizes, int n_in,
                              void* d_out, int out_size)
{
    const float* x     = (const float*)d_in[0];
    const int*   ei    = (const int*)  d_in[1];
    const float* W1    = (const float*)d_in[2];
    const float* b1    = (const float*)d_in[3];
    const float* gamma = (const float*)d_in[4];
    const float* beta  = (const float*)d_in[5];
    const float* W2    = (const float*)d_in[6];
    const float* b2    = (const float*)d_in[7];
    const float* Wp1   = (const float*)d_in[8];
    const float* bp1   = (const float*)d_in[9];
    const float* Wp2   = (const float*)d_in[10];
    const float* bp2   = (const float*)d_in[11];
    const float* Ws1   = (const float*)d_in[12];
    const float* bs1   = (const float*)d_in[13];
    const float* Ws2   = (const float*)d_in[14];
    const float* bs2   = (const float*)d_in[15];
    const float* We1   = (const float*)d_in[16];
    const float* be1   = (const float*)d_in[17];
    const float* We2   = (const float*)d_in[18];
    const float* be2   = (const float*)d_in[19];

    float* out = (float*)d_out;
    float* h_out   = out;
    float* pos_out = out + (size_t)NSPOT * HID;
    float* xs_out  = pos_out + (size_t)NSPOT * 2;
    float* xn_out  = xs_out + (size_t)NSPOT * NGENE;

    float* zp;   cudaGetSymbolAddress((void**)&zp, g_z);
    float* usp;  cudaGetSymbolAddress((void**)&usp, g_uself);
    float* aggp; cudaGetSymbolAddress((void**)&aggp, g_agg);

    const int MB = (NSPOT + 127) / 128;   // 391
    dim3 gN64(1, MB);
    dim3 gBig((NGENE + 127) / 128, MB);   // 16 x 391
    const int EW = (NSPOT * (HID / 4) + 255) / 256;

    // 1. z = x @ W1 + b1   (K=2000)
    gemm_tf32<128, 64, 16, false><<<gN64, 256>>>(x, W1, b1, zp, NSPOT, HID, NGENE);
    // 2. BN stats + elementwise BN+ReLU (in place on g_z)
    bn_stage1<<<500, 64>>>(zp);
    bn_stage2<<<1, 64>>>();
    bn_relu_ew<<<EW, 256>>>(gamma, beta);
    // 3. h = zr @ W2 + b2
    gemm_tf32<128, 64, 32, false><<<gN64, 256>>>(zp, W2, b2, h_out, NSPOT, HID, HID);
    // 4. u_pos = relu(h @ Wp1 + bp1) -> g_agg ; u_self = relu(h @ Ws1 + bs1)
    gemm_tf32<128, 64, 32, true><<<gN64, 256>>>(h_out, Wp1, bp1, aggp, NSPOT, HID, HID);
    gemm_tf32<128, 64, 32, true><<<gN64, 256>>>(h_out, Ws1, bs1, usp, NSPOT, HID, HID);
    // 5. pos = u_pos @ Wp2 + bp2 (before g_agg is reused for scatter)
    pos_head<<<(NSPOT * 32 + 255) / 256, 256>>>(aggp, Wp2, bp2, pos_out);
    // 6. neighbor aggregation into g_agg
    zero_scratch<<<(NSPOT * HID + 255) / 256, 256>>>();
    {
        long tot = (long)NEDGE * 16;
        scatter_h<<<(int)((tot + 255) / 256), 256>>>(h_out, ei);
    }
    mean_ew<<<EW, 256>>>();
    // 7. u_nb = relu(h_agg @ We1 + be1) -> g_z (free now)
    gemm_tf32<128, 64, 32, true><<<gN64, 256>>>(aggp, We1, be1, zp, NSPOT, HID, HID);
    // 8. big output GEMMs
    gemm_tf32<128, 128, 32, false><<<gBig, 256>>>(usp, Ws2, bs2, xs_out, NSPOT, NGENE, HID);
    gemm_tf32<128, 128, 32, false><<<gBig, 256>>>(zp, We2, be2, xn_out, NSPOT, NGENE, HID);

    (void)in_sizes; (void)n_in; (void)out_size;
}

// round 5
// speedup vs baseline: 2.9276x; 1.0915x over previous
#include <cuda_runtime.h>
#include <cstdint>

#define NSPOT 50000
#define NGENE 2000
#define HID   64
#define NEDGE 800000
#define BN_EPS 1e-5f

// ---------------- device scratch (no allocation allowed) ----------------
__device__ float g_z[NSPOT * HID];        // raw z, later reused for u_nb
__device__ float g_uself[NSPOT * HID];    // relu(h@Ws1+bs1)
__device__ float g_agg[NSPOT * HID];      // u_pos, then neighbor raw sums
__device__ int   g_cnt[NSPOT];
__device__ float g_part[500 * 128];
__device__ float g_sc[HID];               // gamma * rstd
__device__ float g_sh[HID];               // beta - mean * gamma * rstd

// ---------------- tf32 helpers ------------------------------------------
__device__ __forceinline__ uint32_t f2tf(float f) {
    uint32_t r; asm("cvt.rna.tf32.f32 %0, %1;" : "=r"(r) : "f"(f)); return r;
}
__device__ __forceinline__ void mma8(float* c, const uint32_t* a, const uint32_t* b) {
    asm volatile(
        "mma.sync.aligned.m16n8k8.row.col.f32.tf32.tf32.f32 "
        "{%0,%1,%2,%3}, {%4,%5,%6,%7}, {%8,%9}, {%0,%1,%2,%3};"
        : "+f"(c[0]), "+f"(c[1]), "+f"(c[2]), "+f"(c[3])
        : "r"(a[0]), "r"(a[1]), "r"(a[2]), "r"(a[3]), "r"(b[0]), "r"(b[1]));
}
__device__ __forceinline__ void cpa16(uint32_t s, const void* g, bool pred) {
    int sz = pred ? 16 : 0;
    asm volatile("cp.async.cg.shared.global [%0], [%1], 16, %2;"
                 :: "r"(s), "l"(g), "r"(sz));
}

// ============ double-buffered cp.async TF32 GEMM (for K=2000) ============
// BM=128, BN=64, BK=32. C = A@B + bias. K arbitrary (zfill), K%4==0, N%4==0.
__global__ __launch_bounds__(256)
void gemm1_db(const float* __restrict__ A, const float* __restrict__ B,
              const float* __restrict__ bias, float* __restrict__ C,
              int M, int N, int K)
{
    constexpr int BM = 128, BN = 64, BK = 32;
    constexpr int ASTR = BK + 4;     // 36
    constexpr int BSTR = BN + 8;     // 72
    extern __shared__ float smem[];
    float* Asf = smem;                         // [2][BM*ASTR]
    float* Bsf = smem + 2 * BM * ASTR;         // [2][BK*BSTR]

    const int tid = threadIdx.x;
    const int lane = tid & 31, wid = tid >> 5;
    const int g = lane >> 2, tg = lane & 3;
    const int rowBase = blockIdx.y * BM;
    // warps: 2 along N, 4 along M; WM=32, WN=32
    const int mW = (wid >> 1) * 32;
    const int nW = (wid & 1) * 32;

    float acc[2][4][4];
#pragma unroll
    for (int i = 0; i < 2; i++)
#pragma unroll
        for (int j = 0; j < 4; j++)
#pragma unroll
            for (int q = 0; q < 4; q++) acc[i][j][q] = 0.f;

    const int KT = (K + BK - 1) / BK;

    auto loadTiles = [&](int buf, int k0) {
        float* Ab = Asf + buf * BM * ASTR;
        float* Bb = Bsf + buf * BK * BSTR;
#pragma unroll
        for (int ii = 0; ii < 4; ii++) {              // A: 1024 chunks / 256 thr
            int i = tid + ii * 256;
            int m = i >> 3, k4 = (i & 7) * 4;
            int r = rowBase + m, gk = k0 + k4;
            cpa16((uint32_t)__cvta_generic_to_shared(Ab + m * ASTR + k4),
                  A + (size_t)r * K + gk, (r < M) && (gk < K));
        }
#pragma unroll
        for (int ii = 0; ii < 2; ii++) {              // B: 512 chunks
            int i = tid + ii * 256;
            int kk = i >> 4, n4 = (i & 15) * 4;
            int gk = k0 + kk;
            cpa16((uint32_t)__cvta_generic_to_shared(Bb + kk * BSTR + n4),
                  B + (size_t)gk * N + n4, (gk < K) && (n4 < N));
        }
    };

    loadTiles(0, 0);
    asm volatile("cp.async.commit_group;");
    int buf = 0;
    for (int kt = 0; kt < KT; kt++) {
        if (kt + 1 < KT) loadTiles(buf ^ 1, (kt + 1) * BK);
        asm volatile("cp.async.commit_group;");
        asm volatile("cp.async.wait_group 1;");
        __syncthreads();
        const float* Ab = Asf + buf * BM * ASTR;
        const float* Bb = Bsf + buf * BK * BSTR;
#pragma unroll
        for (int ks = 0; ks < BK / 8; ks++) {
            uint32_t a[2][4], b[4][2];
#pragma unroll
            for (int i = 0; i < 2; i++) {
                int r0 = mW + i * 16 + g;
                a[i][0] = f2tf(Ab[r0 * ASTR + ks * 8 + tg]);
                a[i][1] = f2tf(Ab[(r0 + 8) * ASTR + ks * 8 + tg]);
                a[i][2] = f2tf(Ab[r0 * ASTR + ks * 8 + tg + 4]);
                a[i][3] = f2tf(Ab[(r0 + 8) * ASTR + ks * 8 + tg + 4]);
            }
#pragma unroll
            for (int j = 0; j < 4; j++) {
                b[j][0] = f2tf(Bb[(ks * 8 + tg) * BSTR + nW + j * 8 + g]);
                b[j][1] = f2tf(Bb[(ks * 8 + tg + 4) * BSTR + nW + j * 8 + g]);
            }
#pragma unroll
            for (int i = 0; i < 2; i++)
#pragma unroll
                for (int j = 0; j < 4; j++)
                    mma8(acc[i][j], a[i], b[j]);
        }
        __syncthreads();
        buf ^= 1;
    }

#pragma unroll
    for (int i = 0; i < 2; i++) {
        int r0 = rowBase + mW + i * 16 + g;
        int r1 = r0 + 8;
#pragma unroll
        for (int j = 0; j < 4; j++) {
            int c = nW + j * 8 + tg * 2;
            float bi0 = __ldg(bias + c), bi1 = __ldg(bias + c + 1);
            if (r0 < M)
                *reinterpret_cast<float2*>(C + (size_t)r0 * N + c) =
                    make_float2(acc[i][j][0] + bi0, acc[i][j][1] + bi1);
            if (r1 < M)
                *reinterpret_cast<float2*>(C + (size_t)r1 * N + c) =
                    make_float2(acc[i][j][2] + bi0, acc[i][j][3] + bi1);
        }
    }
}

// ======== generic TF32 GEMM (single-buffered) with fused A transforms ====
// AMODE: 0 = none, 1 = BN+ReLU per column (g_sc/g_sh), 2 = per-row 1/cnt.
template<int BM, int BN, int BK, bool RELU, int AMODE>
__global__ __launch_bounds__(256)
void gemm_tf32(const float* __restrict__ A, const float* __restrict__ B,
               const float* __restrict__ bias, float* __restrict__ C,
               int M, int N, int K)
{
    constexpr int WARPS_N = BN / 32;
    constexpr int WARPS_M = 8 / WARPS_N;
    constexpr int WM = BM / WARPS_M;
    constexpr int MT = WM / 16;
    constexpr int NT = 4;
    constexpr int ASTR = BK + 4;
    constexpr int BSTR = BN + 8;

    __shared__ __align__(16) uint32_t As[BM * ASTR];
    __shared__ __align__(16) uint32_t Bs[BK * BSTR];

    const int tid = threadIdx.x;
    const int lane = tid & 31, wid = tid >> 5;
    const int g = lane >> 2, tg = lane & 3;
    const int rowBase = blockIdx.y * BM;
    const int colBase = blockIdx.x * BN;
    const int mW = (wid / WARPS_N) * WM;
    const int nW = (wid % WARPS_N) * 32;

    float acc[MT][NT][4];
#pragma unroll
    for (int i = 0; i < MT; i++)
#pragma unroll
        for (int j = 0; j < NT; j++)
#pragma unroll
            for (int q = 0; q < 4; q++) acc[i][j][q] = 0.f;

    for (int k0 = 0; k0 < K; k0 += BK) {
#pragma unroll 2
        for (int i = tid; i < BM * (BK / 4); i += 256) {
            int m = i / (BK / 4), k4 = (i % (BK / 4)) * 4;
            int r = rowBase + m;
            uint4 v = {0u, 0u, 0u, 0u};
            if (r < M) {
                float4 f = *reinterpret_cast<const float4*>(A + (size_t)r * K + k0 + k4);
                if (AMODE == 1) {
                    int kc = k0 + k4;
                    f.x = fmaxf(fmaf(f.x, g_sc[kc+0], g_sh[kc+0]), 0.f);
                    f.y = fmaxf(fmaf(f.y, g_sc[kc+1], g_sh[kc+1]), 0.f);
                    f.z = fmaxf(fmaf(f.z, g_sc[kc+2], g_sh[kc+2]), 0.f);
                    f.w = fmaxf(fmaf(f.w, g_sc[kc+3], g_sh[kc+3]), 0.f);
                } else if (AMODE == 2) {
                    float inv = 1.0f / fmaxf((float)__ldg(&g_cnt[r]), 1.0f);
                    f.x *= inv; f.y *= inv; f.z *= inv; f.w *= inv;
                }
                v.x = f2tf(f.x); v.y = f2tf(f.y); v.z = f2tf(f.z); v.w = f2tf(f.w);
            }
            *reinterpret_cast<uint4*>(&As[m * ASTR + k4]) = v;
        }
#pragma unroll 2
        for (int i = tid; i < BK * (BN / 4); i += 256) {
            int kk = i / (BN / 4), n4 = (i % (BN / 4)) * 4;
            int c = colBase + n4;
            uint4 v = {0u, 0u, 0u, 0u};
            if (c < N) {
                float4 f = *reinterpret_cast<const float4*>(B + (size_t)(k0 + kk) * N + c);
                v.x = f2tf(f.x); v.y = f2tf(f.y); v.z = f2tf(f.z); v.w = f2tf(f.w);
            }
            *reinterpret_cast<uint4*>(&Bs[kk * BSTR + n4]) = v;
        }
        __syncthreads();
#pragma unroll
        for (int ks = 0; ks < BK / 8; ks++) {
            uint32_t a[MT][4], b[NT][2];
#pragma unroll
            for (int i = 0; i < MT; i++) {
                int r0 = mW + i * 16 + g;
                a[i][0] = As[r0 * ASTR + ks * 8 + tg];
                a[i][1] = As[(r0 + 8) * ASTR + ks * 8 + tg];
                a[i][2] = As[r0 * ASTR + ks * 8 + tg + 4];
                a[i][3] = As[(r0 + 8) * ASTR + ks * 8 + tg + 4];
            }
#pragma unroll
            for (int j = 0; j < NT; j++) {
                b[j][0] = Bs[(ks * 8 + tg) * BSTR + nW + j * 8 + g];
                b[j][1] = Bs[(ks * 8 + tg + 4) * BSTR + nW + j * 8 + g];
            }
#pragma unroll
            for (int i = 0; i < MT; i++)
#pragma unroll
                for (int j = 0; j < NT; j++)
                    mma8(acc[i][j], a[i], b[j]);
        }
        __syncthreads();
    }

#pragma unroll
    for (int i = 0; i < MT; i++) {
        int r0 = rowBase + mW + i * 16 + g;
        int r1 = r0 + 8;
#pragma unroll
        for (int j = 0; j < NT; j++) {
            int c = colBase + nW + j * 8 + tg * 2;
            if (c >= N) continue;
            float bi0 = __ldg(bias + c), bi1 = __ldg(bias + c + 1);
            if (r0 < M) {
                float o0 = acc[i][j][0] + bi0, o1 = acc[i][j][1] + bi1;
                if (RELU) { o0 = fmaxf(o0, 0.f); o1 = fmaxf(o1, 0.f); }
                *reinterpret_cast<float2*>(C + (size_t)r0 * N + c) = make_float2(o0, o1);
            }
            if (r1 < M) {
                float o2 = acc[i][j][2] + bi0, o3 = acc[i][j][3] + bi1;
                if (RELU) { o2 = fmaxf(o2, 0.f); o3 = fmaxf(o3, 0.f); }
                *reinterpret_cast<float2*>(C + (size_t)r1 * N + c) = make_float2(o2, o3);
            }
        }
    }
}

// ---------------- BatchNorm statistics (deterministic 2-stage) ----------
__global__ void bn_stage1(const float* __restrict__ z)
{
    const int c = threadIdx.x;
    const int b = blockIdx.x;
    const int r0 = b * 100;
    float s = 0.f, ss = 0.f;
    for (int r = r0; r < r0 + 100; r++) {
        float v = z[(size_t)r * HID + c];
        s += v; ss += v * v;
    }
    g_part[b * 128 + c] = s;
    g_part[b * 128 + 64 + c] = ss;
}

__global__ void bn_stage2(const float* __restrict__ gamma, const float* __restrict__ beta)
{
    const int c = threadIdx.x;
    float s = 0.f, ss = 0.f;
    for (int b = 0; b < 500; b++) {
        s += g_part[b * 128 + c];
        ss += g_part[b * 128 + 64 + c];
    }
    float mu = s / (float)NSPOT;
    float var = ss / (float)NSPOT - mu * mu;
    float rstd = rsqrtf(var + BN_EPS);
    float sc = gamma[c] * rstd;
    g_sc[c] = sc;
    g_sh[c] = beta[c] - mu * sc;
}

// ---------------- pos head: pos = u_pos @ Wp2 + bp2 ---------------------
__global__ __launch_bounds__(256)
void pos_head(const float* __restrict__ upos, const float* __restrict__ Wp2,
              const float* __restrict__ bp2, float* __restrict__ pos)
{
    int gw = (blockIdx.x * blockDim.x + threadIdx.x) >> 5;
    int lane = threadIdx.x & 31;
    if (gw >= NSPOT) return;
    float v0 = upos[(size_t)gw * HID + lane];
    float v1 = upos[(size_t)gw * HID + lane + 32];
    float p0 = v0 * __ldg(Wp2 + lane * 2)     + v1 * __ldg(Wp2 + (lane + 32) * 2);
    float p1 = v0 * __ldg(Wp2 + lane * 2 + 1) + v1 * __ldg(Wp2 + (lane + 32) * 2 + 1);
#pragma unroll
    for (int o = 16; o > 0; o >>= 1) {
        p0 += __shfl_xor_sync(0xffffffffu, p0, o);
        p1 += __shfl_xor_sync(0xffffffffu, p1, o);
    }
    if (lane == 0) {
        pos[(size_t)gw * 2]     = p0 + __ldg(bp2);
        pos[(size_t)gw * 2 + 1] = p1 + __ldg(bp2 + 1);
    }
}

// ---------------- edge aggregation ---------------------------------------
__global__ void zero_scratch()
{
    int i = blockIdx.x * blockDim.x + threadIdx.x;
    if (i < NSPOT * HID) g_agg[i] = 0.f;
    if (i < NSPOT) g_cnt[i] = 0;
}

__global__ void scatter_h(const float* __restrict__ h, const int* __restrict__ ei)
{
    long t = (long)blockIdx.x * blockDim.x + threadIdx.x;
    if (t >= (long)NEDGE * 16) return;
    int e = (int)(t >> 4), p = (int)(t & 15);
    int src = __ldg(ei + e);
    int dst = __ldg(ei + NEDGE + e);
    float4 v = *reinterpret_cast<const float4*>(h + (size_t)src * HID + p * 4);
    float* a = g_agg + (size_t)dst * HID + p * 4;
    if (p == 0) atomicAdd(&g_cnt[dst], 1);
    asm volatile("red.global.add.v4.f32 [%0], {%1,%2,%3,%4};"
                 :: "l"(a), "f"(v.x), "f"(v.y), "f"(v.z), "f"(v.w) : "memory");
}

// ---------------- launch ---------------------------------------------------
extern "C" void kernel_launch(void* const* d_in, const int* in_sizes, int n_in,
                              void* d_out, int out_size)
{
    const float* x     = (const float*)d_in[0];
    const int*   ei    = (const int*)  d_in[1];
    const float* W1    = (const float*)d_in[2];
    const float* b1    = (const float*)d_in[3];
    const float* gamma = (const float*)d_in[4];
    const float* beta  = (const float*)d_in[5];
    const float* W2    = (const float*)d_in[6];
    const float* b2    = (const float*)d_in[7];
    const float* Wp1   = (const float*)d_in[8];
    const float* bp1   = (const float*)d_in[9];
    const float* Wp2   = (const float*)d_in[10];
    const float* bp2   = (const float*)d_in[11];
    const float* Ws1   = (const float*)d_in[12];
    const float* bs1   = (const float*)d_in[13];
    const float* Ws2   = (const float*)d_in[14];
    const float* bs2   = (const float*)d_in[15];
    const float* We1   = (const float*)d_in[16];
    const float* be1   = (const float*)d_in[17];
    const float* We2   = (const float*)d_in[18];
    const float* be2   = (const float*)d_in[19];

    float* out = (float*)d_out;
    float* h_out   = out;
    float* pos_out = out + (size_t)NSPOT * HID;
    float* xs_out  = pos_out + (size_t)NSPOT * 2;
    float* xn_out  = xs_out + (size_t)NSPOT * NGENE;

    float* zp;   cudaGetSymbolAddress((void**)&zp, g_z);
    float* usp;  cudaGetSymbolAddress((void**)&usp, g_uself);
    float* aggp; cudaGetSymbolAddress((void**)&aggp, g_agg);

    const int MB = (NSPOT + 127) / 128;   // 391
    dim3 gN64(1, MB);
    dim3 gBig((NGENE + 127) / 128, MB);

    // 1. z = x @ W1 + b1  (K=2000, cp.async double-buffered)
    {
        constexpr int SMEM = (2 * 128 * 36 + 2 * 32 * 72) * 4;  // 55296 B
        cudaFuncSetAttribute(gemm1_db, cudaFuncAttributeMaxDynamicSharedMemorySize, SMEM);
        gemm1_db<<<gN64, 256, SMEM>>>(x, W1, b1, zp, NSPOT, HID, NGENE);
    }
    // 2. BN stats -> scale/shift
    bn_stage1<<<500, 64>>>(zp);
    bn_stage2<<<1, 64>>>(gamma, beta);
    // 3. h = relu(BN(z)) @ W2 + b2  (BN+ReLU fused into A-load)
    gemm_tf32<128, 64, 32, false, 1><<<gN64, 256>>>(zp, W2, b2, h_out, NSPOT, HID, HID);
    // 4. u_pos = relu(h @ Wp1 + bp1) -> g_agg ; u_self = relu(h @ Ws1 + bs1)
    gemm_tf32<128, 64, 32, true, 0><<<gN64, 256>>>(h_out, Wp1, bp1, aggp, NSPOT, HID, HID);
    gemm_tf32<128, 64, 32, true, 0><<<gN64, 256>>>(h_out, Ws1, bs1, usp, NSPOT, HID, HID);
    // 5. pos = u_pos @ Wp2 + bp2
    pos_head<<<(NSPOT * 32 + 255) / 256, 256>>>(aggp, Wp2, bp2, pos_out);
    // 6. neighbor aggregation (raw sums + counts)
    zero_scratch<<<(NSPOT * HID + 255) / 256, 256>>>();
    {
        long tot = (long)NEDGE * 16;
        scatter_h<<<(int)((tot + 255) / 256), 256>>>(h_out, ei);
    }
    // 7. u_nb = relu(mean(agg) @ We1 + be1) -> g_z  (mean-div fused into A-load)
    gemm_tf32<128, 64, 32, true, 2><<<gN64, 256>>>(aggp, We1, be1, zp, NSPOT, HID, HID);
    // 8. big output GEMMs
    gemm_tf32<128, 128, 32, false, 0><<<gBig, 256>>>(usp, Ws2, bs2, xs_out, NSPOT, NGENE, HID);
    gemm_tf32<128, 128, 32, false, 0><<<gBig, 256>>>(zp, We2, be2, xn_out, NSPOT, NGENE, HID);

    (void)in_sizes; (void)n_in; (void)out_size;
}